// round 1
// baseline (speedup 1.0000x reference)
#include <cuda_runtime.h>
#include <math.h>

#define NN 50000
#define EE 800000
#define HH 128
#define LL 3
#define GG 512
#define OUTD 10

// ---------------- scratch (device globals; no allocations) ----------------
__device__ float d_h0[NN*HH];
__device__ float d_h1[NN*HH];
__device__ float d_aggsum[NN*HH];
__device__ float d_gcnraw[NN*HH];
__device__ float d_deg[NN];
__device__ float d_invdeg[NN];
__device__ float d_invsqrt[NN];
__device__ int   d_counts[GG];
__device__ int   d_offs[GG+1];
__device__ float d_gbuf[GG*(LL+1)*HH];
__device__ float d_naa[LL*4];
__device__ float d_roa[(LL+1)*3];
__device__ float d_cw[LL*4*HH*HH];

// ---------------- small prep kernels ----------------
__global__ void k_zero_node_side() {
    int i = blockIdx.x*blockDim.x + threadIdx.x;
    if (i < NN) d_deg[i] = 0.f;
    if (i < GG) d_counts[i] = 0;
}

__global__ void k_zero_agg() {
    int i = blockIdx.x*blockDim.x + threadIdx.x;
    if (i < NN*HH/4) {
        ((float4*)d_aggsum)[i] = make_float4(0.f,0.f,0.f,0.f);
        ((float4*)d_gcnraw)[i] = make_float4(0.f,0.f,0.f,0.f);
    }
}

__global__ void k_softmax(const float* __restrict__ lna, const float* __restrict__ lro) {
    if (threadIdx.x == 0 && blockIdx.x == 0) {
        for (int l = 0; l < LL; l++) {
            float m = -1e30f;
            for (int j = 0; j < 4; j++) m = fmaxf(m, lna[l*4+j]);
            float e[4], s = 0.f;
            for (int j = 0; j < 4; j++) { e[j] = expf(lna[l*4+j]-m); s += e[j]; }
            for (int j = 0; j < 4; j++) d_naa[l*4+j] = e[j]/s;
        }
        for (int l = 0; l < LL+1; l++) {
            float m = -1e30f;
            for (int j = 0; j < 3; j++) m = fmaxf(m, lro[l*3+j]);
            float e[3], s = 0.f;
            for (int j = 0; j < 3; j++) { e[j] = expf(lro[l*3+j]-m); s += e[j]; }
            for (int j = 0; j < 3; j++) d_roa[l*3+j] = e[j]/s;
        }
    }
}

// Fold the 4 mixture branches into 4 combined 128x128 matrices per layer:
//   out = h @ (w1*W1 + w2*W3 + w3*W4)   [m=0]
//       + gcn_agg @ (w0*W0)             [m=1]
//       + agg_sum @ (w2*W3)             [m=2]
//       + agg_mean @ (w1*W2)            [m=3]
__global__ void k_combine(const float* __restrict__ Wna) {
    int idx = blockIdx.x*blockDim.x + threadIdx.x;
    if (idx >= LL*HH*HH) return;
    int l = idx/(HH*HH), rc = idx%(HH*HH);
    const float* Wb = Wna + (size_t)l*5*HH*HH;
    float w0 = d_naa[l*4+0], w1 = d_naa[l*4+1], w2 = d_naa[l*4+2], w3 = d_naa[l*4+3];
    float W0 = Wb[0*HH*HH+rc], W1 = Wb[1*HH*HH+rc], W2 = Wb[2*HH*HH+rc];
    float W3 = Wb[3*HH*HH+rc], W4 = Wb[4*HH*HH+rc];
    float* cw = d_cw + (size_t)l*4*HH*HH;
    cw[0*HH*HH+rc] = w1*W1 + w2*W3 + w3*W4;
    cw[1*HH*HH+rc] = w0*W0;
    cw[2*HH*HH+rc] = w2*W3;
    cw[3*HH*HH+rc] = w1*W2;
}

__global__ void k_deg(const int* __restrict__ dst) {
    int e = blockIdx.x*blockDim.x + threadIdx.x;
    if (e < EE) atomicAdd(&d_deg[dst[e]], 1.0f);
}

__global__ void k_nodeprep(const int* __restrict__ batch) {
    int n = blockIdx.x*blockDim.x + threadIdx.x;
    if (n < NN) {
        float d = fmaxf(d_deg[n], 1.0f);
        d_invdeg[n]  = 1.0f/d;
        d_invsqrt[n] = 1.0f/sqrtf(d);
        atomicAdd(&d_counts[batch[n]], 1);
    }
}

__global__ void k_offs() {
    if (threadIdx.x == 0 && blockIdx.x == 0) {
        int a = 0; d_offs[0] = 0;
        for (int g = 0; g < GG; g++) { a += d_counts[g]; d_offs[g+1] = a; }
    }
}

// ---------------- lin1 GEMM: h0 = x @ W + b ----------------
__global__ void __launch_bounds__(256) k_lin1(const float* __restrict__ x,
                                              const float* __restrict__ W,
                                              const float* __restrict__ b) {
    __shared__ float Ws[32][128];
    __shared__ float Xs[64][33];
    int t = threadIdx.x;
    int row0 = blockIdx.x*64;
    int rg = (t>>4)<<2;      // 0..60 step 4
    int cg = (t&15)<<3;      // 0..120 step 8
    float acc[4][8];
    #pragma unroll
    for (int i = 0; i < 4; i++)
        #pragma unroll
        for (int j = 0; j < 8; j++) acc[i][j] = 0.f;

    for (int kc = 0; kc < HH; kc += 32) {
        for (int i = t; i < 32*128; i += 256) {
            int kk = i>>7, cc = i&127;
            Ws[kk][cc] = W[(kc+kk)*HH + cc];
        }
        for (int i = t; i < 64*32; i += 256) {
            int r = i>>5, kk = i&31;
            int gr = row0 + r;
            Xs[r][kk] = (gr < NN) ? x[(size_t)gr*HH + kc + kk] : 0.f;
        }
        __syncthreads();
        #pragma unroll
        for (int k = 0; k < 32; k++) {
            float a[4], bb[8];
            #pragma unroll
            for (int i = 0; i < 4; i++) a[i] = Xs[rg+i][k];
            #pragma unroll
            for (int j = 0; j < 8; j++) bb[j] = Ws[k][cg+j];
            #pragma unroll
            for (int i = 0; i < 4; i++)
                #pragma unroll
                for (int j = 0; j < 8; j++) acc[i][j] = fmaf(a[i], bb[j], acc[i][j]);
        }
        __syncthreads();
    }
    #pragma unroll
    for (int i = 0; i < 4; i++) {
        int gr = row0 + rg + i;
        if (gr < NN) {
            #pragma unroll
            for (int j = 0; j < 8; j++)
                d_h0[(size_t)gr*HH + cg + j] = acc[i][j] + b[cg+j];
        }
    }
}

// ---------------- edge aggregation: one warp per edge ----------------
__global__ void k_agg(int l, const int* __restrict__ src, const int* __restrict__ dst) {
    int gt = blockIdx.x*blockDim.x + threadIdx.x;
    int w = gt >> 5, lane = gt & 31;
    if (w >= EE) return;
    const float* hin = (l & 1) ? d_h1 : d_h0;
    int s = src[w], d2 = dst[w];
    float4 v = ((const float4*)(hin + (size_t)s*HH))[lane];
    float isw = d_invsqrt[s];
    atomicAdd(((float4*)(d_aggsum + (size_t)d2*HH)) + lane, v);
    float4 v2 = make_float4(v.x*isw, v.y*isw, v.z*isw, v.w*isw);
    atomicAdd(((float4*)(d_gcnraw + (size_t)d2*HH)) + lane, v2);
}

// ---------------- per-layer node transform: 4-pass [N,512]@[512,128] + ReLU ----
__global__ void __launch_bounds__(256) k_layer(int l) {
    __shared__ float Ws[32][128];
    __shared__ float Xs[64][33];
    __shared__ float srow[64];
    const float* hin  = (l & 1) ? d_h1 : d_h0;
    float*       hout = (l & 1) ? d_h0 : d_h1;
    const float* cwl = d_cw + (size_t)l*4*HH*HH;
    int t = threadIdx.x;
    int row0 = blockIdx.x*64;
    int rg = (t>>4)<<2;
    int cg = (t&15)<<3;
    float acc[4][8];
    #pragma unroll
    for (int i = 0; i < 4; i++)
        #pragma unroll
        for (int j = 0; j < 8; j++) acc[i][j] = 0.f;

    for (int p = 0; p < 4; p++) {
        const float* X = (p == 0) ? hin : (p == 1 ? d_gcnraw : d_aggsum);
        const float* W = cwl + p*HH*HH;
        __syncthreads();
        if (t < 64) {
            int gr = row0 + t;
            float s = 1.f;
            if (gr < NN) {
                if (p == 1) s = d_invsqrt[gr];       // gcn_agg = gcnraw * invsqrt[dst]
                else if (p == 3) s = d_invdeg[gr];   // agg_mean = agg_sum / deg
            }
            srow[t] = s;
        }
        __syncthreads();
        for (int kc = 0; kc < HH; kc += 32) {
            for (int i = t; i < 32*128; i += 256) {
                int kk = i>>7, cc = i&127;
                Ws[kk][cc] = W[(kc+kk)*HH + cc];
            }
            for (int i = t; i < 64*32; i += 256) {
                int r = i>>5, kk = i&31;
                int gr = row0 + r;
                Xs[r][kk] = (gr < NN) ? X[(size_t)gr*HH + kc + kk]*srow[r] : 0.f;
            }
            __syncthreads();
            #pragma unroll
            for (int k = 0; k < 32; k++) {
                float a[4], bb[8];
                #pragma unroll
                for (int i = 0; i < 4; i++) a[i] = Xs[rg+i][k];
                #pragma unroll
                for (int j = 0; j < 8; j++) bb[j] = Ws[k][cg+j];
                #pragma unroll
                for (int i = 0; i < 4; i++)
                    #pragma unroll
                    for (int j = 0; j < 8; j++) acc[i][j] = fmaf(a[i], bb[j], acc[i][j]);
            }
            __syncthreads();
        }
    }
    #pragma unroll
    for (int i = 0; i < 4; i++) {
        int gr = row0 + rg + i;
        if (gr < NN) {
            #pragma unroll
            for (int j = 0; j < 8; j++)
                hout[(size_t)gr*HH + cg + j] = fmaxf(acc[i][j], 0.f);
        }
    }
}

// ---------------- readout: one block per graph (batch is sorted) ----------------
__global__ void k_readout(int layer) {
    const float* h = (layer & 1) ? d_h1 : d_h0;
    int g = blockIdx.x, d = threadIdx.x;
    int s0 = d_offs[g], s1 = d_offs[g+1];
    float s = 0.f, m = -1e30f;
    for (int n = s0; n < s1; n++) {
        float v = h[(size_t)n*HH + d];
        s += v; m = fmaxf(m, v);
    }
    int cnt = s1 - s0;
    float mean = s / fmaxf((float)cnt, 1.0f);
    float mx = (cnt > 0) ? m : 0.f;
    float w0 = d_roa[layer*3+0], w1 = d_roa[layer*3+1], w2 = d_roa[layer*3+2];
    d_gbuf[(size_t)g*((LL+1)*HH) + layer*HH + d] = w0*mean + w1*mx + w2*s;
}

// ---------------- fused head: relu(g @ loW + lob) @ cW + cb ----------------
__global__ void k_final(const float* __restrict__ loW, const float* __restrict__ lob,
                        const float* __restrict__ cW,  const float* __restrict__ cb,
                        float* __restrict__ out) {
    __shared__ float gs[(LL+1)*HH];
    __shared__ float ts[HH];
    int g = blockIdx.x, t = threadIdx.x;
    for (int i = t; i < (LL+1)*HH; i += HH) gs[i] = d_gbuf[(size_t)g*((LL+1)*HH) + i];
    __syncthreads();
    float a = lob[t];
    for (int k = 0; k < (LL+1)*HH; k++) a = fmaf(gs[k], loW[k*HH + t], a);
    ts[t] = fmaxf(a, 0.f);
    __syncthreads();
    if (t < OUTD) {
        float o = cb[t];
        for (int k = 0; k < HH; k++) o = fmaf(ts[k], cW[k*OUTD + t], o);
        out[g*OUTD + t] = o;
    }
}

// ---------------- launch ----------------
extern "C" void kernel_launch(void* const* d_in, const int* in_sizes, int n_in,
                              void* d_out, int out_size) {
    const float* x      = (const float*)d_in[0];
    const int*   ei     = (const int*)  d_in[1];
    const int*   batch  = (const int*)  d_in[2];
    const float* lin1_W = (const float*)d_in[3];
    const float* lin1_b = (const float*)d_in[4];
    const float* Wna    = (const float*)d_in[5];
    const float* lna    = (const float*)d_in[6];
    const float* lro    = (const float*)d_in[7];
    const float* loW    = (const float*)d_in[8];
    const float* lob    = (const float*)d_in[9];
    const float* cW     = (const float*)d_in[10];
    const float* cb     = (const float*)d_in[11];
    const int* src = ei;
    const int* dst = ei + EE;
    float* out = (float*)d_out;

    k_zero_node_side<<<(NN+255)/256, 256>>>();
    k_softmax<<<1, 32>>>(lna, lro);
    k_combine<<<(LL*HH*HH+255)/256, 256>>>(Wna);
    k_deg<<<(EE+255)/256, 256>>>(dst);
    k_nodeprep<<<(NN+255)/256, 256>>>(batch);
    k_offs<<<1, 32>>>();
    k_lin1<<<(NN+63)/64, 256>>>(x, lin1_W, lin1_b);
    k_readout<<<GG, HH>>>(0);

    for (int l = 0; l < LL; l++) {
        k_zero_agg<<<(NN*HH/4+255)/256, 256>>>();
        k_agg<<<(EE*32)/256, 256>>>(l, src, dst);
        k_layer<<<(NN+63)/64, 256>>>(l);
        k_readout<<<GG, HH>>>(l+1);
    }
    k_final<<<GG, HH>>>(loW, lob, cW, cb, out);
}

// round 2
// speedup vs baseline: 1.1988x; 1.1988x over previous
#include <cuda_runtime.h>
#include <math.h>

#define NN 50000
#define EE 800000
#define HH 128
#define LL 3
#define GG 512
#define OUTD 10

// ---------------- scratch (device globals; no allocations) ----------------
__device__ float d_h0[NN*HH];
__device__ float d_h1[NN*HH];
__device__ float d_aggsum[NN*HH];
__device__ float d_gcn[NN*HH];       // pre-scaled by invsqrt[dst]
__device__ float d_invdeg[NN];
__device__ float d_invsqrt[NN];
__device__ int   d_indeg[NN];
__device__ int   d_rowoff[NN+1];
__device__ int   d_cursor[NN];
__device__ int   d_csrc[EE];
__device__ float d_csrw[EE];
__device__ int   d_counts[GG];
__device__ int   d_offs[GG+1];
__device__ float d_gbuf[GG*(LL+1)*HH];
__device__ float d_naa[LL*4];
__device__ float d_roa[(LL+1)*3];
__device__ float d_cw[LL*4*HH*HH];

// ---------------- small prep kernels ----------------
__global__ void k_zero_prep() {
    int i = blockIdx.x*blockDim.x + threadIdx.x;
    if (i < NN) d_indeg[i] = 0;
    if (i < GG) d_counts[i] = 0;
}

__global__ void k_softmax(const float* __restrict__ lna, const float* __restrict__ lro) {
    if (threadIdx.x == 0 && blockIdx.x == 0) {
        for (int l = 0; l < LL; l++) {
            float m = -1e30f;
            for (int j = 0; j < 4; j++) m = fmaxf(m, lna[l*4+j]);
            float e[4], s = 0.f;
            for (int j = 0; j < 4; j++) { e[j] = expf(lna[l*4+j]-m); s += e[j]; }
            for (int j = 0; j < 4; j++) d_naa[l*4+j] = e[j]/s;
        }
        for (int l = 0; l < LL+1; l++) {
            float m = -1e30f;
            for (int j = 0; j < 3; j++) m = fmaxf(m, lro[l*3+j]);
            float e[3], s = 0.f;
            for (int j = 0; j < 3; j++) { e[j] = expf(lro[l*3+j]-m); s += e[j]; }
            for (int j = 0; j < 3; j++) d_roa[l*3+j] = e[j]/s;
        }
    }
}

// Fold the 4 mixture branches into 4 combined 128x128 matrices per layer:
//   out = h @ (w1*W1 + w3*W4)  +  gcn_agg @ (w0*W0)
//       + agg_sum @ (w2*W3 applied to both h+agg via GIN)  + agg_mean @ (w1*W2)
// (GIN contributes w2*W3 to both the h-path and the agg_sum-path.)
__global__ void k_combine(const float* __restrict__ Wna) {
    int idx = blockIdx.x*blockDim.x + threadIdx.x;
    if (idx >= LL*HH*HH) return;
    int l = idx/(HH*HH), rc = idx%(HH*HH);
    const float* Wb = Wna + (size_t)l*5*HH*HH;
    float w0 = d_naa[l*4+0], w1 = d_naa[l*4+1], w2 = d_naa[l*4+2], w3 = d_naa[l*4+3];
    float W0 = Wb[0*HH*HH+rc], W1 = Wb[1*HH*HH+rc], W2 = Wb[2*HH*HH+rc];
    float W3 = Wb[3*HH*HH+rc], W4 = Wb[4*HH*HH+rc];
    float* cw = d_cw + (size_t)l*4*HH*HH;
    cw[0*HH*HH+rc] = w1*W1 + w2*W3 + w3*W4;  // applied to h
    cw[1*HH*HH+rc] = w0*W0;                  // applied to gcn_agg (pre-scaled)
    cw[2*HH*HH+rc] = w2*W3;                  // applied to agg_sum
    cw[3*HH*HH+rc] = w1*W2;                  // applied to agg_mean
}

__global__ void k_deg(const int* __restrict__ dst) {
    int e = blockIdx.x*blockDim.x + threadIdx.x;
    if (e < EE) atomicAdd(&d_indeg[dst[e]], 1);
}

// single-block exclusive prefix scan over d_indeg -> d_rowoff
__global__ void __launch_bounds__(1024) k_prefix() {
    __shared__ int ps[1024];
    int t = threadIdx.x;
    const int CH = (NN + 1023)/1024;
    int b = t*CH, e = min(b + CH, NN);
    int s = 0;
    for (int i = b; i < e; i++) s += d_indeg[i];
    ps[t] = s;
    __syncthreads();
    // Hillis-Steele inclusive scan
    for (int off = 1; off < 1024; off <<= 1) {
        int v = (t >= off) ? ps[t-off] : 0;
        __syncthreads();
        ps[t] += v;
        __syncthreads();
    }
    int run = (t == 0) ? 0 : ps[t-1];
    for (int i = b; i < e; i++) { d_rowoff[i] = run; run += d_indeg[i]; }
    if (t == 0) d_rowoff[NN] = EE;
}

__global__ void k_nodeprep(const int* __restrict__ batch) {
    int n = blockIdx.x*blockDim.x + threadIdx.x;
    if (n < NN) {
        float d = fmaxf((float)d_indeg[n], 1.0f);
        d_invdeg[n]  = 1.0f/d;
        d_invsqrt[n] = rsqrtf(d);
        d_cursor[n]  = d_rowoff[n];
        atomicAdd(&d_counts[batch[n]], 1);
    }
}

__global__ void k_scatter(const int* __restrict__ src, const int* __restrict__ dst) {
    int e = blockIdx.x*blockDim.x + threadIdx.x;
    if (e >= EE) return;
    int s = src[e], d2 = dst[e];
    int pos = atomicAdd(&d_cursor[d2], 1);
    d_csrc[pos] = s;
    d_csrw[pos] = d_invsqrt[s];
}

__global__ void k_offs() {
    if (threadIdx.x == 0 && blockIdx.x == 0) {
        int a = 0; d_offs[0] = 0;
        for (int g = 0; g < GG; g++) { a += d_counts[g]; d_offs[g+1] = a; }
    }
}

// ---------------- lin1 GEMM: h0 = x @ W + b ----------------
__global__ void __launch_bounds__(256) k_lin1(const float* __restrict__ x,
                                              const float* __restrict__ W,
                                              const float* __restrict__ b) {
    __shared__ float Ws[32][128];
    __shared__ float Xs[64][33];
    int t = threadIdx.x;
    int row0 = blockIdx.x*64;
    int rg = (t>>4)<<2;
    int cg = (t&15)<<3;
    float acc[4][8];
    #pragma unroll
    for (int i = 0; i < 4; i++)
        #pragma unroll
        for (int j = 0; j < 8; j++) acc[i][j] = 0.f;

    for (int kc = 0; kc < HH; kc += 32) {
        for (int i = t; i < 32*128; i += 256) {
            int kk = i>>7, cc = i&127;
            Ws[kk][cc] = W[(kc+kk)*HH + cc];
        }
        for (int i = t; i < 64*32; i += 256) {
            int r = i>>5, kk = i&31;
            int gr = row0 + r;
            Xs[r][kk] = (gr < NN) ? x[(size_t)gr*HH + kc + kk] : 0.f;
        }
        __syncthreads();
        #pragma unroll
        for (int k = 0; k < 32; k++) {
            float a[4], bb[8];
            #pragma unroll
            for (int i = 0; i < 4; i++) a[i] = Xs[rg+i][k];
            #pragma unroll
            for (int j = 0; j < 8; j++) bb[j] = Ws[k][cg+j];
            #pragma unroll
            for (int i = 0; i < 4; i++)
                #pragma unroll
                for (int j = 0; j < 8; j++) acc[i][j] = fmaf(a[i], bb[j], acc[i][j]);
        }
        __syncthreads();
    }
    #pragma unroll
    for (int i = 0; i < 4; i++) {
        int gr = row0 + rg + i;
        if (gr < NN) {
            #pragma unroll
            for (int j = 0; j < 8; j++)
                d_h0[(size_t)gr*HH + cg + j] = acc[i][j] + b[cg+j];
        }
    }
}

// ---------------- CSR gather-reduce: one warp per node, no atomics ----------
__global__ void __launch_bounds__(256) k_gather(int l) {
    int gt = blockIdx.x*blockDim.x + threadIdx.x;
    int n = gt >> 5, lane = gt & 31;
    if (n >= NN) return;
    const float* hin = (l & 1) ? d_h1 : d_h0;
    int beg = d_rowoff[n], end = d_rowoff[n+1];
    float4 s0 = make_float4(0.f,0.f,0.f,0.f);
    float4 s1 = make_float4(0.f,0.f,0.f,0.f);
    int i = beg;
    for (; i + 2 <= end; i += 2) {
        int sA = d_csrc[i],   sB = d_csrc[i+1];
        float wA = d_csrw[i], wB = d_csrw[i+1];
        float4 vA = ((const float4*)(hin + (size_t)sA*HH))[lane];
        float4 vB = ((const float4*)(hin + (size_t)sB*HH))[lane];
        s0.x += vA.x + vB.x; s0.y += vA.y + vB.y;
        s0.z += vA.z + vB.z; s0.w += vA.w + vB.w;
        s1.x = fmaf(vA.x, wA, fmaf(vB.x, wB, s1.x));
        s1.y = fmaf(vA.y, wA, fmaf(vB.y, wB, s1.y));
        s1.z = fmaf(vA.z, wA, fmaf(vB.z, wB, s1.z));
        s1.w = fmaf(vA.w, wA, fmaf(vB.w, wB, s1.w));
    }
    if (i < end) {
        int sA = d_csrc[i]; float wA = d_csrw[i];
        float4 vA = ((const float4*)(hin + (size_t)sA*HH))[lane];
        s0.x += vA.x; s0.y += vA.y; s0.z += vA.z; s0.w += vA.w;
        s1.x = fmaf(vA.x, wA, s1.x); s1.y = fmaf(vA.y, wA, s1.y);
        s1.z = fmaf(vA.z, wA, s1.z); s1.w = fmaf(vA.w, wA, s1.w);
    }
    float isd = d_invsqrt[n];
    ((float4*)(d_aggsum + (size_t)n*HH))[lane] = s0;
    ((float4*)(d_gcn    + (size_t)n*HH))[lane] =
        make_float4(s1.x*isd, s1.y*isd, s1.z*isd, s1.w*isd);
}

// ---------------- per-layer node transform: 4-pass [N,512]@[512,128] + ReLU ----
__global__ void __launch_bounds__(256) k_layer(int l) {
    __shared__ float Ws[32][128];
    __shared__ float Xs[64][33];
    __shared__ float srow[64];
    const float* hin  = (l & 1) ? d_h1 : d_h0;
    float*       hout = (l & 1) ? d_h0 : d_h1;
    const float* cwl = d_cw + (size_t)l*4*HH*HH;
    int t = threadIdx.x;
    int row0 = blockIdx.x*64;
    int rg = (t>>4)<<2;
    int cg = (t&15)<<3;
    float acc[4][8];
    #pragma unroll
    for (int i = 0; i < 4; i++)
        #pragma unroll
        for (int j = 0; j < 8; j++) acc[i][j] = 0.f;

    for (int p = 0; p < 4; p++) {
        const float* X = (p == 0) ? hin : (p == 1 ? d_gcn : d_aggsum);
        const float* W = cwl + p*HH*HH;
        __syncthreads();
        if (t < 64) {
            int gr = row0 + t;
            float s = 1.f;
            if (gr < NN && p == 3) s = d_invdeg[gr];   // agg_mean = agg_sum / deg
            srow[t] = s;
        }
        __syncthreads();
        for (int kc = 0; kc < HH; kc += 32) {
            for (int i = t; i < 32*128; i += 256) {
                int kk = i>>7, cc = i&127;
                Ws[kk][cc] = W[(kc+kk)*HH + cc];
            }
            for (int i = t; i < 64*32; i += 256) {
                int r = i>>5, kk = i&31;
                int gr = row0 + r;
                Xs[r][kk] = (gr < NN) ? X[(size_t)gr*HH + kc + kk]*srow[r] : 0.f;
            }
            __syncthreads();
            #pragma unroll
            for (int k = 0; k < 32; k++) {
                float a[4], bb[8];
                #pragma unroll
                for (int i = 0; i < 4; i++) a[i] = Xs[rg+i][k];
                #pragma unroll
                for (int j = 0; j < 8; j++) bb[j] = Ws[k][cg+j];
                #pragma unroll
                for (int i = 0; i < 4; i++)
                    #pragma unroll
                    for (int j = 0; j < 8; j++) acc[i][j] = fmaf(a[i], bb[j], acc[i][j]);
            }
            __syncthreads();
        }
    }
    #pragma unroll
    for (int i = 0; i < 4; i++) {
        int gr = row0 + rg + i;
        if (gr < NN) {
            #pragma unroll
            for (int j = 0; j < 8; j++)
                hout[(size_t)gr*HH + cg + j] = fmaxf(acc[i][j], 0.f);
        }
    }
}

// ---------------- readout: one block per graph (batch is sorted) ----------------
__global__ void k_readout(int layer) {
    const float* h = (layer & 1) ? d_h1 : d_h0;
    int g = blockIdx.x, d = threadIdx.x;
    int s0 = d_offs[g], s1 = d_offs[g+1];
    float s = 0.f, m = -1e30f;
    for (int n = s0; n < s1; n++) {
        float v = h[(size_t)n*HH + d];
        s += v; m = fmaxf(m, v);
    }
    int cnt = s1 - s0;
    float mean = s / fmaxf((float)cnt, 1.0f);
    float mx = (cnt > 0) ? m : 0.f;
    float w0 = d_roa[layer*3+0], w1 = d_roa[layer*3+1], w2 = d_roa[layer*3+2];
    d_gbuf[(size_t)g*((LL+1)*HH) + layer*HH + d] = w0*mean + w1*mx + w2*s;
}

// ---------------- fused head: relu(g @ loW + lob) @ cW + cb ----------------
__global__ void k_final(const float* __restrict__ loW, const float* __restrict__ lob,
                        const float* __restrict__ cW,  const float* __restrict__ cb,
                        float* __restrict__ out) {
    __shared__ float gs[(LL+1)*HH];
    __shared__ float ts[HH];
    int g = blockIdx.x, t = threadIdx.x;
    for (int i = t; i < (LL+1)*HH; i += HH) gs[i] = d_gbuf[(size_t)g*((LL+1)*HH) + i];
    __syncthreads();
    float a = lob[t];
    for (int k = 0; k < (LL+1)*HH; k++) a = fmaf(gs[k], loW[k*HH + t], a);
    ts[t] = fmaxf(a, 0.f);
    __syncthreads();
    if (t < OUTD) {
        float o = cb[t];
        for (int k = 0; k < HH; k++) o = fmaf(ts[k], cW[k*OUTD + t], o);
        out[g*OUTD + t] = o;
    }
}

// ---------------- launch ----------------
extern "C" void kernel_launch(void* const* d_in, const int* in_sizes, int n_in,
                              void* d_out, int out_size) {
    const float* x      = (const float*)d_in[0];
    const int*   ei     = (const int*)  d_in[1];
    const int*   batch  = (const int*)  d_in[2];
    const float* lin1_W = (const float*)d_in[3];
    const float* lin1_b = (const float*)d_in[4];
    const float* Wna    = (const float*)d_in[5];
    const float* lna    = (const float*)d_in[6];
    const float* lro    = (const float*)d_in[7];
    const float* loW    = (const float*)d_in[8];
    const float* lob    = (const float*)d_in[9];
    const float* cW     = (const float*)d_in[10];
    const float* cb     = (const float*)d_in[11];
    const int* src = ei;
    const int* dst = ei + EE;
    float* out = (float*)d_out;

    k_zero_prep<<<(NN+255)/256, 256>>>();
    k_softmax<<<1, 32>>>(lna, lro);
    k_combine<<<(LL*HH*HH+255)/256, 256>>>(Wna);
    k_deg<<<(EE+255)/256, 256>>>(dst);
    k_prefix<<<1, 1024>>>();
    k_nodeprep<<<(NN+255)/256, 256>>>(batch);
    k_scatter<<<(EE+255)/256, 256>>>(src, dst);
    k_offs<<<1, 32>>>();
    k_lin1<<<(NN+63)/64, 256>>>(x, lin1_W, lin1_b);
    k_readout<<<GG, HH>>>(0);

    for (int l = 0; l < LL; l++) {
        k_gather<<<(NN*32+255)/256, 256>>>(l);
        k_layer<<<(NN+63)/64, 256>>>(l);
        k_readout<<<GG, HH>>>(l+1);
    }
    k_final<<<GG, HH>>>(loW, lob, cW, cb, out);
}